// round 2
// baseline (speedup 1.0000x reference)
#include <cuda_runtime.h>

// GCN with learnable edge gates; output = log_softmax(h3[index]) only.
// Pruned 3-hop dependence cone. R2: vectorized edge scans (8 edges/thread,
// 128-bit loads), fused dinv+compact, fused tail (scatter2+y3+softmax).

#define NN 50000
#define NE 800000
#define DH 64
#define DIN 128
#define NC 10

// ---------------- device scratch ----------------
__device__ float g_deg[NN];                  // deg, then dinv in-place
__device__ unsigned char g_m1[NN], g_m2[NN], g_m3[NN];
__device__ int g_el1[NE], g_el2[NE], g_el3[NE];
__device__ int g_n1, g_n2, g_n3, g_c1, g_c2, g_c3;
__device__ int g_l1[NN], g_l2[NN], g_l3[NN];
__device__ float g_y1[(size_t)NN * DH];
__device__ float g_h1[(size_t)NN * DH];
__device__ float g_y2[(size_t)NN * DH];
__device__ float g_h2[(size_t)NN * DH];
__device__ float g_y3[(size_t)NN * NC];
__device__ int g_is64;

__device__ __forceinline__ float sigf(float v) { return 1.f / (1.f + expf(-v)); }

__device__ __forceinline__ int eidx(const void* ei, long long i) {
    if (g_is64) return (int)((const long long*)ei)[i];
    return ((const int*)ei)[i];
}

// Load 8 consecutive dst indices starting at edge `base` (base%8==0, base+8<=E).
__device__ __forceinline__ void load_dst8(const void* ei, int E, int base, int* dl) {
    if (g_is64) {
        const ulonglong2* p = (const ulonglong2*)((const long long*)ei + E);
        #pragma unroll
        for (int q = 0; q < 4; q++) {
            ulonglong2 v = p[base / 2 + q];
            dl[2 * q] = (int)v.x; dl[2 * q + 1] = (int)v.y;
        }
    } else {
        const int4* p = (const int4*)((const int*)ei + E);
        #pragma unroll
        for (int q = 0; q < 2; q++) {
            int4 v = p[base / 4 + q];
            dl[4 * q] = v.x; dl[4 * q + 1] = v.y; dl[4 * q + 2] = v.z; dl[4 * q + 3] = v.w;
        }
    }
}

// ---------------- kernels ----------------

__global__ void k_init(const void* ei, const int* idxp) {
    int t = blockIdx.x * blockDim.x + threadIdx.x;
    if (t == 0) {
        g_n1 = 0; g_n2 = 0; g_n3 = 0;
        g_c1 = 0; g_c2 = 0; g_c3 = 0;
        const int* w = (const int*)ei;
        int any = 0;
        #pragma unroll
        for (int k = 0; k < 32; k++) any |= w[2 * k + 1];
        g_is64 = (any == 0) ? 1 : 0;
    }
    int v0 = t * 4;
    if (v0 >= NN) return;
    ((float4*)g_deg)[t] = make_float4(1.f, 1.f, 1.f, 1.f);
    uchar4 z = make_uchar4(0, 0, 0, 0);
    ((uchar4*)g_m1)[t] = z;
    ((uchar4*)g_m2)[t] = z;
    ((uchar4*)g_m3)[t] = z;
    int idx = *idxp;
    if (idx >= v0 && idx < v0 + 4) g_m1[idx] = 1;   // same thread owns these bytes
}

// Full scan: degree accumulation + frontier1 (edges into `index`). 8 edges/thread.
__global__ void k_scan1(const void* ei, const float* wp, const int* idxp, int E) {
    int t = blockIdx.x * blockDim.x + threadIdx.x;
    int base = t * 8;
    if (base >= E) return;
    int idx = *idxp;
    if (base + 8 <= E) {
        int dl[8]; float w[8];
        load_dst8(ei, E, base, dl);
        const float4* wv = (const float4*)wp;
        #pragma unroll
        for (int q = 0; q < 2; q++) {
            float4 v = wv[base / 4 + q];
            w[4 * q] = v.x; w[4 * q + 1] = v.y; w[4 * q + 2] = v.z; w[4 * q + 3] = v.w;
        }
        #pragma unroll
        for (int k = 0; k < 8; k++) {
            atomicAdd(&g_deg[dl[k]], sigf(w[k]));
            if (dl[k] == idx) {
                int s = eidx(ei, base + k);
                g_m1[s] = 1;
                int p = atomicAdd(&g_n1, 1);
                g_el1[p] = base + k;
            }
        }
    } else {
        for (int e = base; e < E; e++) {
            int d = eidx(ei, (long long)E + e);
            atomicAdd(&g_deg[d], sigf(wp[e]));
            if (d == idx) {
                int s = eidx(ei, e);
                g_m1[s] = 1;
                int p = atomicAdd(&g_n1, 1);
                g_el1[p] = e;
            }
        }
    }
}

// Generic frontier expansion: m_in -> m_out, collect edges whose dst is in m_in.
// First PROP threads propagate mask bytes (byte stores only where set: avoids
// clobbering concurrent edge-thread byte writes), rest scan 8 edges each.
#define PROP ((NN + 15) / 16)

__device__ __forceinline__ void frontier_scan(const void* ei, int E, int t,
                                              const unsigned char* m_in,
                                              unsigned char* m_out,
                                              int* counter, int* elist) {
    if (t < PROP) {
        int b0 = t * 16;
        uint4 a = ((const uint4*)m_in)[t];
        if (a.x | a.y | a.z | a.w) {
            const unsigned char* src = m_in + b0;
            #pragma unroll
            for (int k = 0; k < 16; k++)
                if (src[k]) m_out[b0 + k] = 1;
        }
        return;
    }
    int base = (t - PROP) * 8;
    if (base >= E) return;
    if (base + 8 <= E) {
        int dl[8];
        load_dst8(ei, E, base, dl);
        #pragma unroll
        for (int k = 0; k < 8; k++) {
            if (m_in[dl[k]]) {
                int s = eidx(ei, base + k);
                m_out[s] = 1;
                int p = atomicAdd(counter, 1);
                elist[p] = base + k;
            }
        }
    } else {
        for (int e = base; e < E; e++) {
            int d = eidx(ei, (long long)E + e);
            if (m_in[d]) {
                int s = eidx(ei, e);
                m_out[s] = 1;
                int p = atomicAdd(counter, 1);
                elist[p] = e;
            }
        }
    }
}

__global__ void k_scan2(const void* ei, int E) {
    int t = blockIdx.x * blockDim.x + threadIdx.x;
    frontier_scan(ei, E, t, g_m1, g_m2, &g_n2, g_el2);
}

__global__ void k_scan3(const void* ei, int E) {
    int t = blockIdx.x * blockDim.x + threadIdx.x;
    frontier_scan(ei, E, t, g_m2, g_m3, &g_n3, g_el3);
}

// Compact masks into node lists; dinv; zero h1 rows for frontier2.
__global__ void k_compact() {
    int t = blockIdx.x * blockDim.x + threadIdx.x;
    int v0 = t * 4;
    if (v0 >= NN) return;
    float4 dg = ((const float4*)g_deg)[t];
    dg.x = rsqrtf(dg.x); dg.y = rsqrtf(dg.y); dg.z = rsqrtf(dg.z); dg.w = rsqrtf(dg.w);
    ((float4*)g_deg)[t] = dg;
    uchar4 a1 = ((const uchar4*)g_m1)[t];
    uchar4 a2 = ((const uchar4*)g_m2)[t];
    uchar4 a3 = ((const uchar4*)g_m3)[t];
    unsigned char b1[4] = {a1.x, a1.y, a1.z, a1.w};
    unsigned char b2[4] = {a2.x, a2.y, a2.z, a2.w};
    unsigned char b3[4] = {a3.x, a3.y, a3.z, a3.w};
    #pragma unroll
    for (int k = 0; k < 4; k++) {
        int v = v0 + k;
        if (b1[k]) {
            int p = atomicAdd(&g_c1, 1);
            g_l1[p] = v;
        }
        if (b2[k]) {
            int p = atomicAdd(&g_c2, 1);
            g_l2[p] = v;
            float4* r = (float4*)&g_h1[(size_t)v * DH];
            float4 z = make_float4(0.f, 0.f, 0.f, 0.f);
            #pragma unroll
            for (int j = 0; j < DH / 4; j++) r[j] = z;
        }
        if (b3[k]) {
            int p = atomicAdd(&g_c3, 1);
            g_l3[p] = v;
        }
    }
}

// y1[v] = x[v] @ W1 for v in frontier3. One warp per node; W1 in smem.
__global__ void k_xw1(const float* x, const float* W1) {
    __shared__ float sW[DIN * DH];
    __shared__ float sx[8][DIN];
    for (int i = threadIdx.x; i < DIN * DH; i += blockDim.x) sW[i] = W1[i];
    __syncthreads();
    int warp = threadIdx.x >> 5, lane = threadIdx.x & 31;
    int gw = blockIdx.x * (blockDim.x >> 5) + warp;
    int nw = gridDim.x * (blockDim.x >> 5);
    int c3 = g_c3;
    for (int i = gw; i < c3; i += nw) {
        int v = g_l3[i];
        const float4* xr = (const float4*)(x + (size_t)v * DIN);
        ((float4*)sx[warp])[lane] = xr[lane];     // 32 lanes x 16B = 512B row
        __syncwarp();
        float a0 = 0.f, a1 = 0.f;
        #pragma unroll 16
        for (int k = 0; k < DIN; k++) {
            float xv = sx[warp][k];
            a0 = fmaf(xv, sW[k * DH + lane], a0);
            a1 = fmaf(xv, sW[k * DH + lane + 32], a1);
        }
        float* yr = &g_y1[(size_t)v * DH];
        yr[lane] = a0; yr[lane + 32] = a1;
        __syncwarp();
    }
}

// h1[dst] += norm * y1[src] over EL3 edges, plus self-loops for frontier2.
__global__ void k_scatter1(const void* ei, const float* wp, int E) {
    int lane = threadIdx.x & 31;
    int gw = (blockIdx.x * blockDim.x + threadIdx.x) >> 5;
    int nw = (gridDim.x * blockDim.x) >> 5;
    int n3 = g_n3, c2 = g_c2;
    int tot = n3 + c2;
    for (int i = gw; i < tot; i += nw) {
        int s, d; float norm;
        if (i < n3) {
            int e = g_el3[i];
            s = eidx(ei, e); d = eidx(ei, (long long)E + e);
            norm = g_deg[s] * sigf(wp[e]) * g_deg[d];
        } else {
            s = d = g_l2[i - n3];
            float dv = g_deg[s];
            norm = dv * dv;
        }
        const float* ys = &g_y1[(size_t)s * DH];
        float* hd = &g_h1[(size_t)d * DH];
        atomicAdd(&hd[lane],      norm * ys[lane]);
        atomicAdd(&hd[lane + 32], norm * ys[lane + 32]);
    }
}

// y2[v] = relu(h1[v] + b1) @ W2 for v in frontier2.
__global__ void k_xw2(const float* W2, const float* b1) {
    __shared__ float sW[DH * DH];
    __shared__ float sb[DH];
    __shared__ float sx[8][DH];
    for (int i = threadIdx.x; i < DH * DH; i += blockDim.x) sW[i] = W2[i];
    if (threadIdx.x < DH) sb[threadIdx.x] = b1[threadIdx.x];
    __syncthreads();
    int warp = threadIdx.x >> 5, lane = threadIdx.x & 31;
    int gw = blockIdx.x * (blockDim.x >> 5) + warp;
    int nw = gridDim.x * (blockDim.x >> 5);
    int c2 = g_c2;
    for (int i = gw; i < c2; i += nw) {
        int v = g_l2[i];
        const float* hr = &g_h1[(size_t)v * DH];
        sx[warp][lane]      = fmaxf(hr[lane]      + sb[lane],      0.f);
        sx[warp][lane + 32] = fmaxf(hr[lane + 32] + sb[lane + 32], 0.f);
        __syncwarp();
        float a0 = 0.f, a1 = 0.f;
        #pragma unroll 16
        for (int k = 0; k < DH; k++) {
            float xv = sx[warp][k];
            a0 = fmaf(xv, sW[k * DH + lane], a0);
            a1 = fmaf(xv, sW[k * DH + lane + 32], a1);
        }
        float* yr = &g_y2[(size_t)v * DH];
        yr[lane] = a0; yr[lane + 32] = a1;
        __syncwarp();
    }
}

// Fused tail (single block): zero h2 rows, scatter2, y3, log-softmax.
__global__ void k_tail(const void* ei, const float* wp, const int* idxp,
                       const float* W3, const float* b2, const float* b3,
                       float* out, int E) {
    int tid = threadIdx.x, lane = tid & 31, warp = tid >> 5;   // 8 warps
    int c1 = g_c1, n2 = g_n2, n1 = g_n1;
    // A: zero h2 rows for frontier1
    for (int i = warp; i < c1; i += 8) {
        int v = g_l1[i];
        float* r = &g_h2[(size_t)v * DH];
        r[lane] = 0.f; r[lane + 32] = 0.f;
    }
    __syncthreads();
    // B: scatter2 (edges into frontier1 + self-loops)
    int tot = n2 + c1;
    for (int i = warp; i < tot; i += 8) {
        int s, d; float norm;
        if (i < n2) {
            int e = g_el2[i];
            s = eidx(ei, e); d = eidx(ei, (long long)E + e);
            norm = g_deg[s] * sigf(wp[e]) * g_deg[d];
        } else {
            s = d = g_l1[i - n2];
            float dv = g_deg[s];
            norm = dv * dv;
        }
        const float* ys = &g_y2[(size_t)s * DH];
        float* hd = &g_h2[(size_t)d * DH];
        atomicAdd(&hd[lane],      norm * ys[lane]);
        atomicAdd(&hd[lane + 32], norm * ys[lane + 32]);
    }
    __syncthreads();
    // C: y3[v] = relu(h2[v] + b2) @ W3 for v in frontier1
    for (int i = warp; i < c1; i += 8) {
        int v = g_l1[i];
        if (lane < NC) {
            float acc = 0.f;
            const float* hr = &g_h2[(size_t)v * DH];
            #pragma unroll
            for (int k = 0; k < DH; k++) {
                float hv = fmaxf(hr[k] + b2[k], 0.f);
                acc = fmaf(hv, W3[k * NC + lane], acc);
            }
            g_y3[(size_t)v * NC + lane] = acc;
        }
    }
    __syncthreads();
    // D: final combine + log-softmax
    __shared__ float sv[NC];
    int idx = *idxp;
    float di = g_deg[idx];
    if (tid < NC) {
        float acc = b3[tid] + di * di * g_y3[(size_t)idx * NC + tid];
        for (int i = 0; i < n1; i++) {
            int e = g_el1[i];
            int s = eidx(ei, e);
            float norm = g_deg[s] * sigf(wp[e]) * di;
            acc = fmaf(norm, g_y3[(size_t)s * NC + tid], acc);
        }
        sv[tid] = acc;
    }
    __syncthreads();
    if (tid == 0) {
        float m = sv[0];
        #pragma unroll
        for (int t = 1; t < NC; t++) m = fmaxf(m, sv[t]);
        float ssum = 0.f;
        #pragma unroll
        for (int t = 0; t < NC; t++) ssum += expf(sv[t] - m);
        float l = m + logf(ssum);
        #pragma unroll
        for (int t = 0; t < NC; t++) out[t] = sv[t] - l;
    }
}

// ---------------- launch ----------------
extern "C" void kernel_launch(void* const* d_in, const int* in_sizes, int n_in,
                              void* d_out, int out_size) {
    const float* x   = (const float*)d_in[0];
    const void*  ei  = d_in[1];
    const float* wp  = (const float*)d_in[2];
    const float* W1  = (const float*)d_in[3];
    const float* b1  = (const float*)d_in[4];
    const float* W2  = (const float*)d_in[5];
    const float* b2  = (const float*)d_in[6];
    const float* W3  = (const float*)d_in[7];
    const float* b3  = (const float*)d_in[8];
    const int*  idxp = (const int*)d_in[9];
    float* out = (float*)d_out;

    int E = in_sizes[2];
    if (E > NE) E = NE;

    int nt_init = (NN + 3) / 4;
    int nt_s1   = (E + 7) / 8;
    int nt_s23  = PROP + (E + 7) / 8;

    k_init<<<(nt_init + 255) / 256, 256>>>(ei, idxp);
    k_scan1<<<(nt_s1 + 255) / 256, 256>>>(ei, wp, idxp, E);
    k_scan2<<<(nt_s23 + 255) / 256, 256>>>(ei, E);
    k_scan3<<<(nt_s23 + 255) / 256, 256>>>(ei, E);
    k_compact<<<(nt_init + 255) / 256, 256>>>();
    k_xw1<<<120, 256>>>(x, W1);
    k_scatter1<<<64, 256>>>(ei, wp, E);
    k_xw2<<<32, 256>>>(W2, b1);
    k_tail<<<1, 256>>>(ei, wp, idxp, W3, b2, b3, out, E);
}

// round 5
// speedup vs baseline: 1.0097x; 1.0097x over previous
#include <cuda_runtime.h>

// GCN with learnable edge gates; output = log_softmax(h3[index]) only.
// Pruned 3-hop dependence cone. R5: smem-bitmask frontier scans; FIX: never
// pass __device__ symbols as host-side kernel arguments (R3/R4 bug).

#define NN 50000
#define NE 800000
#define DH 64
#define DIN 128
#define NC 10
#define NWORDS ((NN + 31) / 32)     // 1563

// ---------------- device scratch ----------------
__device__ float g_deg[NN];                        // deg, then dinv in-place
__device__ unsigned g_bm1[NWORDS], g_bm2[NWORDS], g_bm3[NWORDS];
__device__ int g_el1[4096], g_el2[65536], g_el3[NE];
__device__ int g_n1, g_n2, g_n3, g_c1, g_c2, g_c3;
__device__ int g_l1[NN], g_l2[NN], g_l3[NN];
__device__ float g_y1[(size_t)NN * DH];
__device__ float g_h1[(size_t)NN * DH];
__device__ float g_y2[(size_t)NN * DH];
__device__ float g_h2[(size_t)NN * DH];
__device__ float g_y3[(size_t)NN * NC];
__device__ int g_is64;

__device__ __forceinline__ float sigf(float v) { return 1.f / (1.f + expf(-v)); }

__device__ __forceinline__ int eidx_r(const void* ei, long long i, int is64) {
    if (is64) return (int)((const long long*)ei)[i];
    return ((const int*)ei)[i];
}
__device__ __forceinline__ int eidx(const void* ei, long long i) {
    return eidx_r(ei, i, g_is64);
}

// ---------------- kernels ----------------

// Zero state + dtype sniff + seed bm1 with `index`.
__global__ void k_init(const void* ei, const int* idxp) {
    int t = blockIdx.x * blockDim.x + threadIdx.x;
    if (t == 0) {
        g_n1 = 0; g_n2 = 0; g_n3 = 0;
        g_c1 = 0; g_c2 = 0; g_c3 = 0;
        // int64 edge values < 50000 => high words all zero across 32 entries.
        const int* w = (const int*)ei;
        int any = 0;
        #pragma unroll
        for (int k = 0; k < 32; k++) any |= w[2 * k + 1];
        g_is64 = (any == 0) ? 1 : 0;
    }
    if (t < NWORDS) {
        int idx = *idxp;
        g_bm1[t] = ((idx >> 5) == t) ? (1u << (idx & 31)) : 0u;
        g_bm2[t] = 0u;
        g_bm3[t] = 0u;
    }
    if (t * 4 < NN)
        ((float4*)g_deg)[t] = make_float4(1.f, 1.f, 1.f, 1.f);  // self-loop
}

// Full scan: degree accumulation + frontier1 (edges into `index`). 4 edges/thread.
__global__ void k_scan1(const void* ei, const float* wp, const int* idxp, int E) {
    int t = blockIdx.x * blockDim.x + threadIdx.x;
    int base = t * 4;
    if (base >= E) return;
    int idx = *idxp;
    int is64 = g_is64;
    if (base + 4 <= E) {
        int dl[4];
        if (is64) {
            const ulonglong2* p = (const ulonglong2*)((const long long*)ei + E);
            ulonglong2 v0 = p[base / 2], v1 = p[base / 2 + 1];
            dl[0] = (int)v0.x; dl[1] = (int)v0.y; dl[2] = (int)v1.x; dl[3] = (int)v1.y;
        } else {
            int4 v = ((const int4*)((const int*)ei + E))[base / 4];
            dl[0] = v.x; dl[1] = v.y; dl[2] = v.z; dl[3] = v.w;
        }
        float4 wv = ((const float4*)wp)[base / 4];
        float w[4] = {wv.x, wv.y, wv.z, wv.w};
        #pragma unroll
        for (int k = 0; k < 4; k++) {
            atomicAdd(&g_deg[dl[k]], sigf(w[k]));
            if (dl[k] == idx) {
                int s = eidx_r(ei, base + k, is64);
                atomicOr(&g_bm1[s >> 5], 1u << (s & 31));
                int p = atomicAdd(&g_n1, 1);
                g_el1[p] = base + k;
            }
        }
    } else {
        for (int e = base; e < E; e++) {
            int d = eidx_r(ei, (long long)E + e, is64);
            atomicAdd(&g_deg[d], sigf(wp[e]));
            if (d == idx) {
                int s = eidx_r(ei, e, is64);
                atomicOr(&g_bm1[s >> 5], 1u << (s & 31));
                int p = atomicAdd(&g_n1, 1);
                g_el1[p] = e;
            }
        }
    }
}

// Frontier expansion with smem bitmask. LEVEL selects which device-global
// masks/lists to use (no pointers passed from host!).
//   LEVEL=2: test bm1,       write bm2, list el2/n2
//   LEVEL=3: test bm1|bm2,   write bm3, list el3/n3
template <int LEVEL>
__device__ __forceinline__ void expand_body(const void* ei, int E) {
    __shared__ unsigned sbm[NWORDS];
    for (int i = threadIdx.x; i < NWORDS; i += blockDim.x)
        sbm[i] = (LEVEL == 2) ? g_bm1[i] : (g_bm1[i] | g_bm2[i]);
    __syncthreads();
    int t = blockIdx.x * blockDim.x + threadIdx.x;
    int base = t * 2;
    if (base >= E) return;
    int is64 = g_is64;
    int nlocal = (base + 2 <= E) ? 2 : 1;
    int dl[2];
    if (is64) {
        const ulonglong2* p = (const ulonglong2*)((const long long*)ei + E);
        ulonglong2 v = p[base / 2];
        dl[0] = (int)v.x; dl[1] = (int)v.y;
    } else {
        int2 v = ((const int2*)((const int*)ei + E))[base / 2];
        dl[0] = v.x; dl[1] = v.y;
    }
    #pragma unroll
    for (int k = 0; k < 2; k++) {
        if (k >= nlocal) break;
        int d = dl[k];
        if ((sbm[d >> 5] >> (d & 31)) & 1u) {
            int s = eidx_r(ei, base + k, is64);
            if (LEVEL == 2) {
                atomicOr(&g_bm2[s >> 5], 1u << (s & 31));
                int p = atomicAdd(&g_n2, 1);
                g_el2[p] = base + k;
            } else {
                atomicOr(&g_bm3[s >> 5], 1u << (s & 31));
                int p = atomicAdd(&g_n3, 1);
                g_el3[p] = base + k;
            }
        }
    }
}

__global__ void k_expand2(const void* ei, int E) { expand_body<2>(ei, E); }
__global__ void k_expand3(const void* ei, int E) { expand_body<3>(ei, E); }

// dinv + compact frontiers (f1=bm1, f2=bm1|bm2, f3=bm1|bm2|bm3); zero h1 rows.
__global__ void k_compact() {
    int t = blockIdx.x * blockDim.x + threadIdx.x;
    if (t * 4 < NN) {
        float4 dg = ((const float4*)g_deg)[t];
        dg.x = rsqrtf(dg.x); dg.y = rsqrtf(dg.y);
        dg.z = rsqrtf(dg.z); dg.w = rsqrtf(dg.w);
        ((float4*)g_deg)[t] = dg;
    }
    if (t >= NWORDS) return;
    unsigned w1 = g_bm1[t];
    unsigned w2 = w1 | g_bm2[t];
    unsigned w3 = w2 | g_bm3[t];
    int b0 = t << 5;
    if (w1) {
        int p = atomicAdd(&g_c1, __popc(w1));
        unsigned m = w1;
        while (m) {
            int b = __ffs(m) - 1; m &= m - 1;
            g_l1[p++] = b0 + b;
        }
    }
    if (w2) {
        int p = atomicAdd(&g_c2, __popc(w2));
        unsigned m = w2;
        while (m) {
            int b = __ffs(m) - 1; m &= m - 1;
            int v = b0 + b;
            g_l2[p++] = v;
            float4* r = (float4*)&g_h1[(size_t)v * DH];
            float4 z = make_float4(0.f, 0.f, 0.f, 0.f);
            #pragma unroll
            for (int j = 0; j < DH / 4; j++) r[j] = z;
        }
    }
    if (w3) {
        int p = atomicAdd(&g_c3, __popc(w3));
        unsigned m = w3;
        while (m) {
            int b = __ffs(m) - 1; m &= m - 1;
            g_l3[p++] = b0 + b;
        }
    }
}

// y1[v] = x[v] @ W1 for v in frontier3. One warp per node; W1 in smem.
__global__ void k_xw1(const float* x, const float* W1) {
    __shared__ float sW[DIN * DH];
    __shared__ float sx[8][DIN];
    for (int i = threadIdx.x; i < DIN * DH; i += blockDim.x) sW[i] = W1[i];
    __syncthreads();
    int warp = threadIdx.x >> 5, lane = threadIdx.x & 31;
    int gw = blockIdx.x * (blockDim.x >> 5) + warp;
    int nw = gridDim.x * (blockDim.x >> 5);
    int c3 = g_c3;
    for (int i = gw; i < c3; i += nw) {
        int v = g_l3[i];
        const float4* xr = (const float4*)(x + (size_t)v * DIN);
        ((float4*)sx[warp])[lane] = xr[lane];
        __syncwarp();
        float a0 = 0.f, a1 = 0.f;
        #pragma unroll 16
        for (int k = 0; k < DIN; k++) {
            float xv = sx[warp][k];
            a0 = fmaf(xv, sW[k * DH + lane], a0);
            a1 = fmaf(xv, sW[k * DH + lane + 32], a1);
        }
        float* yr = &g_y1[(size_t)v * DH];
        yr[lane] = a0; yr[lane + 32] = a1;
        __syncwarp();
    }
}

// h1[dst] += norm * y1[src] over EL3 edges, plus self-loops for frontier2.
__global__ void k_scatter1(const void* ei, const float* wp, int E) {
    int lane = threadIdx.x & 31;
    int gw = (blockIdx.x * blockDim.x + threadIdx.x) >> 5;
    int nw = (gridDim.x * blockDim.x) >> 5;
    int n3 = g_n3, c2 = g_c2;
    int tot = n3 + c2;
    for (int i = gw; i < tot; i += nw) {
        int s, d; float norm;
        if (i < n3) {
            int e = g_el3[i];
            s = eidx(ei, e); d = eidx(ei, (long long)E + e);
            norm = g_deg[s] * sigf(wp[e]) * g_deg[d];
        } else {
            s = d = g_l2[i - n3];
            float dv = g_deg[s];
            norm = dv * dv;
        }
        const float* ys = &g_y1[(size_t)s * DH];
        float* hd = &g_h1[(size_t)d * DH];
        atomicAdd(&hd[lane],      norm * ys[lane]);
        atomicAdd(&hd[lane + 32], norm * ys[lane + 32]);
    }
}

// y2[v] = relu(h1[v] + b1) @ W2 for v in frontier2.
__global__ void k_xw2(const float* W2, const float* b1) {
    __shared__ float sW[DH * DH];
    __shared__ float sb[DH];
    __shared__ float sx[8][DH];
    for (int i = threadIdx.x; i < DH * DH; i += blockDim.x) sW[i] = W2[i];
    if (threadIdx.x < DH) sb[threadIdx.x] = b1[threadIdx.x];
    __syncthreads();
    int warp = threadIdx.x >> 5, lane = threadIdx.x & 31;
    int gw = blockIdx.x * (blockDim.x >> 5) + warp;
    int nw = gridDim.x * (blockDim.x >> 5);
    int c2 = g_c2;
    for (int i = gw; i < c2; i += nw) {
        int v = g_l2[i];
        const float* hr = &g_h1[(size_t)v * DH];
        sx[warp][lane]      = fmaxf(hr[lane]      + sb[lane],      0.f);
        sx[warp][lane + 32] = fmaxf(hr[lane + 32] + sb[lane + 32], 0.f);
        __syncwarp();
        float a0 = 0.f, a1 = 0.f;
        #pragma unroll 16
        for (int k = 0; k < DH; k++) {
            float xv = sx[warp][k];
            a0 = fmaf(xv, sW[k * DH + lane], a0);
            a1 = fmaf(xv, sW[k * DH + lane + 32], a1);
        }
        float* yr = &g_y2[(size_t)v * DH];
        yr[lane] = a0; yr[lane + 32] = a1;
        __syncwarp();
    }
}

// Fused tail (single block): zero h2 rows, scatter2, y3, log-softmax.
__global__ void k_tail(const void* ei, const float* wp, const int* idxp,
                       const float* W3, const float* b2, const float* b3,
                       float* out, int E) {
    int tid = threadIdx.x, lane = tid & 31, warp = tid >> 5;   // 8 warps
    int c1 = g_c1, n2 = g_n2, n1 = g_n1;
    for (int i = warp; i < c1; i += 8) {
        int v = g_l1[i];
        float* r = &g_h2[(size_t)v * DH];
        r[lane] = 0.f; r[lane + 32] = 0.f;
    }
    __syncthreads();
    int tot = n2 + c1;
    for (int i = warp; i < tot; i += 8) {
        int s, d; float norm;
        if (i < n2) {
            int e = g_el2[i];
            s = eidx(ei, e); d = eidx(ei, (long long)E + e);
            norm = g_deg[s] * sigf(wp[e]) * g_deg[d];
        } else {
            s = d = g_l1[i - n2];
            float dv = g_deg[s];
            norm = dv * dv;
        }
        const float* ys = &g_y2[(size_t)s * DH];
        float* hd = &g_h2[(size_t)d * DH];
        atomicAdd(&hd[lane],      norm * ys[lane]);
        atomicAdd(&hd[lane + 32], norm * ys[lane + 32]);
    }
    __syncthreads();
    for (int i = warp; i < c1; i += 8) {
        int v = g_l1[i];
        if (lane < NC) {
            float acc = 0.f;
            const float* hr = &g_h2[(size_t)v * DH];
            #pragma unroll
            for (int k = 0; k < DH; k++) {
                float hv = fmaxf(hr[k] + b2[k], 0.f);
                acc = fmaf(hv, W3[k * NC + lane], acc);
            }
            g_y3[(size_t)v * NC + lane] = acc;
        }
    }
    __syncthreads();
    __shared__ float sv[NC];
    int idx = *idxp;
    float di = g_deg[idx];
    if (tid < NC) {
        float acc = b3[tid] + di * di * g_y3[(size_t)idx * NC + tid];
        for (int i = 0; i < n1; i++) {
            int e = g_el1[i];
            int s = eidx(ei, e);
            float norm = g_deg[s] * sigf(wp[e]) * di;
            acc = fmaf(norm, g_y3[(size_t)s * NC + tid], acc);
        }
        sv[tid] = acc;
    }
    __syncthreads();
    if (tid == 0) {
        float m = sv[0];
        #pragma unroll
        for (int t = 1; t < NC; t++) m = fmaxf(m, sv[t]);
        float ssum = 0.f;
        #pragma unroll
        for (int t = 0; t < NC; t++) ssum += expf(sv[t] - m);
        float l = m + logf(ssum);
        #pragma unroll
        for (int t = 0; t < NC; t++) out[t] = sv[t] - l;
    }
}

// ---------------- launch ----------------
extern "C" void kernel_launch(void* const* d_in, const int* in_sizes, int n_in,
                              void* d_out, int out_size) {
    const float* x   = (const float*)d_in[0];
    const void*  ei  = d_in[1];
    const float* wp  = (const float*)d_in[2];
    const float* W1  = (const float*)d_in[3];
    const float* b1  = (const float*)d_in[4];
    const float* W2  = (const float*)d_in[5];
    const float* b2  = (const float*)d_in[6];
    const float* W3  = (const float*)d_in[7];
    const float* b3  = (const float*)d_in[8];
    const int*  idxp = (const int*)d_in[9];
    float* out = (float*)d_out;

    int E = in_sizes[2];
    if (E > NE) E = NE;

    int nt_init = (NN + 3) / 4;                 // 12500 (> NWORDS)
    int nt_s1   = (E + 3) / 4;
    int nt_s23  = (E + 1) / 2;

    k_init<<<(nt_init + 255) / 256, 256>>>(ei, idxp);
    k_scan1<<<(nt_s1 + 255) / 256, 256>>>(ei, wp, idxp, E);
    k_expand2<<<(nt_s23 + 255) / 256, 256>>>(ei, E);
    k_expand3<<<(nt_s23 + 255) / 256, 256>>>(ei, E);
    k_compact<<<(nt_init + 255) / 256, 256>>>();
    k_xw1<<<120, 256>>>(x, W1);
    k_scatter1<<<64, 256>>>(ei, wp, E);
    k_xw2<<<32, 256>>>(W2, b1);
    k_tail<<<1, 256>>>(ei, wp, idxp, W3, b2, b3, out, E);
}